// round 8
// baseline (speedup 1.0000x reference)
#include <cuda_runtime.h>
#include <cstdint>

// HexPool: out[i, :] = max_{k<7} x[neigh_indices[i,k], :]
// x: (655362, 64) f32 ; neigh_indices: (163842, 7) int32 ; out: (163842, 64) f32
//
// Combines the two measured wins:
//  - R7: __stcs (evict-first) output stores -> x + idx stay L2-resident,
//    DRAM at compulsory floor (~42 MB output write-through). 24.6 -> 22.1 us.
//  - R6 geometry: 8 threads (quarter-warp) per row, each thread owns float4
//    cols c and c+8 -> 14 independent gather LDG.128s per thread (2x MLP),
//    half the SHFL/ALU overhead (measured ALU 27%->12%, issue 29%->15%).
// Per warp instruction: 4 rows x 128B contiguous segments, fully coalesced.
//
// grid = ceil(163842/32) = 5121; tail clamps row + predicates store; all
// lanes stay converged through every __shfl_sync.

#define N_OUT 163842
#define KNB   7
#define VEC_PER_ROW 16      // 64 floats / 4
#define BLOCK_THREADS 256
#define ROWS_PER_BLOCK 32   // 256 threads / 8 threads per row

__device__ __forceinline__ void fmax4(float4& m, const float4& v) {
    m.x = fmaxf(m.x, v.x);
    m.y = fmaxf(m.y, v.y);
    m.z = fmaxf(m.z, v.z);
    m.w = fmaxf(m.w, v.w);
}

__global__ __launch_bounds__(BLOCK_THREADS) void hexpool_kernel(
    const float4* __restrict__ x,          // viewed as [n_in][16] float4
    const int* __restrict__ idx,           // [N_OUT][7] int32
    float4* __restrict__ out)               // [N_OUT][16] float4
{
    const int tid = blockIdx.x * BLOCK_THREADS + threadIdx.x;
    const int row_raw = tid >> 3;                    // 8 threads per row
    const int row = row_raw < N_OUT ? row_raw : (N_OUT - 1);
    const int col = tid & 7;                         // float4 col 0..7 (also owns col+8)

    const int lane = threadIdx.x & 31;
    const int q_base = lane & 24;                    // quarter-warp start lane
    const int sub = lane & 7;

    // Lanes sub<7 of each quarter-warp load the 7 indices for this row.
    int my_idx = 0;
    if (sub < KNB) {
        my_idx = __ldg(&idx[row * KNB + sub]);
    }

    const float NEG = -3.402823466e+38f;
    float4 m0 = make_float4(NEG, NEG, NEG, NEG);
    float4 m1 = make_float4(NEG, NEG, NEG, NEG);

    #pragma unroll
    for (int k = 0; k < KNB; ++k) {
        int j = __shfl_sync(0xFFFFFFFFu, my_idx, q_base + k);
        const float4* rowp = &x[(long long)j * VEC_PER_ROW];
        float4 v0 = __ldg(rowp + col);
        float4 v1 = __ldg(rowp + col + 8);
        fmax4(m0, v0);
        fmax4(m1, v1);
    }

    if (row_raw < N_OUT) {
        float4* orow = &out[(long long)row_raw * VEC_PER_ROW];
        __stcs(orow + col,     m0);   // evict-first: don't displace x's L2 lines
        __stcs(orow + col + 8, m1);
    }
}

extern "C" void kernel_launch(void* const* d_in, const int* in_sizes, int n_in,
                              void* d_out, int out_size)
{
    const float4* x   = (const float4*)d_in[0];
    const int*    idx = (const int*)d_in[1];
    float4*       out = (float4*)d_out;

    const int grid = (N_OUT + ROWS_PER_BLOCK - 1) / ROWS_PER_BLOCK;  // 5121
    hexpool_kernel<<<grid, BLOCK_THREADS>>>(x, idx, out);
}